// round 15
// baseline (speedup 1.0000x reference)
#include <cuda_runtime.h>
#include <cstdint>

// KPConv fused: FFMA2 + compaction + QT=8 (3 CTA/SM) + balanced flattened
// Stage-C GEMM + warp-fused A+B + WTP=12 (16B-aligned A-pair loads).
// M=50000, H=32, K=15 kernel pts, Cin=Cout=64.

#define QT 8
#define HN 32
#define KK 15
#define KP 16
#define CC 64
#define NTHREADS 256
#define MAXN 65536
#define WTP 12       // wT q-stride (floats): rows 16B-aligned for pair loads
#define PTP 10       // part q-stride (floats)

typedef unsigned long long ull;

__device__ __forceinline__ ull pack2(float lo, float hi) {
    ull r; asm("mov.b64 %0, {%1, %2};" : "=l"(r) : "f"(lo), "f"(hi)); return r;
}
__device__ __forceinline__ void fma2(ull& d, ull a, ull b) {
    asm("fma.rn.f32x2 %0, %1, %2, %0;" : "+l"(d) : "l"(a), "l"(b));
}
__device__ __forceinline__ float2 unpack2(ull v) {
    float2 r; asm("mov.b64 {%0, %1}, %2;" : "=f"(r.x), "=f"(r.y) : "l"(v)); return r;
}
__device__ __forceinline__ ull lds64(uint32_t a) {
    ull r; asm volatile("ld.shared.b64 %0, [%1];" : "=l"(r) : "r"(a)); return r;
}
__device__ __forceinline__ void lds2(uint32_t a, ull& x, ull& y) {
    asm volatile("ld.shared.v2.u64 {%0, %1}, [%2];" : "=l"(x), "=l"(y) : "r"(a));
}
__device__ __forceinline__ void sts64(uint32_t a, ull v) {
    asm volatile("st.shared.b64 [%0], %1;" :: "r"(a), "l"(v) : "memory");
}

__device__ float g_colsum[MAXN];

// 4 rows per warp, float4 reads, 3-level 8-lane reduce.
__global__ void colsum_kernel(const float* __restrict__ s_feats, int N) {
    const int lane = threadIdx.x & 31;
    const int gw = (blockIdx.x * blockDim.x + threadIdx.x) >> 5;
    const int r = gw * 4 + (lane >> 3);
    const int rr = (r < N) ? r : (N - 1);
    const float4* fp = reinterpret_cast<const float4*>(s_feats + (size_t)rr * CC);
    const float4 a = fp[(lane & 7) * 2];
    const float4 b = fp[(lane & 7) * 2 + 1];
    float s = a.x + a.y + a.z + a.w + b.x + b.y + b.z + b.w;
    s += __shfl_xor_sync(0xffffffffu, s, 4);
    s += __shfl_xor_sync(0xffffffffu, s, 2);
    s += __shfl_xor_sync(0xffffffffu, s, 1);
    if ((lane & 7) == 0 && r < N) g_colsum[r] = s;
}

struct __align__(16) Smem {
    union {
        struct {
            float infl[QT][HN][KP];     // compacted influence rows
            int   sidx[QT][HN];
            float kp[KK][3];
        } a;
        float part[8][CC][PTP];         // stage-C partials (overwrites a)
    } u;
    float wT[KK][CC][WTP];              // weighted, transposed [k][c][q]
    float nnum[QT];
};

__global__ __launch_bounds__(NTHREADS, 3)
void kpconv_kernel(const float* __restrict__ q_points,
                   const float* __restrict__ s_points,
                   const float* __restrict__ s_feats,
                   const void* __restrict__ nbr_idx_raw,
                   const float* __restrict__ kernel_points,
                   const float* __restrict__ weights,
                   float* __restrict__ out,
                   int M, int N)
{
    extern __shared__ __align__(16) char smem_raw[];
    Smem& sm = *reinterpret_cast<Smem*>(smem_raw);
    const int tid = threadIdx.x;
    const int m0 = blockIdx.x * QT;

    // ---- dtype probe: int64 indices (<= N) have zero odd 32-bit words ----
    const int* iw = reinterpret_cast<const int*>(nbr_idx_raw);
    int oddbits = iw[2 * tid + 1] | iw[2 * (tid + NTHREADS) + 1];
    if (tid < KK * 3)
        reinterpret_cast<float*>(sm.u.a.kp)[tid] = kernel_points[tid];
    const int idx64 = !__syncthreads_or(oddbits != 0);

    // ================= Stage A+B fused per warp (warp = query) =============
    {
        const int lane = tid & 31;
        const int ml = tid >> 5;
        const unsigned lt = (1u << lane) - 1u;
        const int m = m0 + ml;

        // ---- A: influence + compaction + neighbor count ----
        bool valid = false;
        int si = 0;
        float rx = 0.f, ry = 0.f, rz = 0.f, cs = 0.f;
        if (m < M) {
            long long gi;
            if (idx64)
                gi = reinterpret_cast<const long long*>(nbr_idx_raw)[(long long)m * HN + lane];
            else
                gi = reinterpret_cast<const int*>(nbr_idx_raw)[(long long)m * HN + lane];
            if (gi < (long long)N) { valid = true; si = (int)gi; }
        }
        if (valid) {
            rx = s_points[si * 3 + 0] - q_points[m * 3 + 0];
            ry = s_points[si * 3 + 1] - q_points[m * 3 + 1];
            rz = s_points[si * 3 + 2] - q_points[m * 3 + 2];
            cs = g_colsum[si];
        }
        float inf[KK];
        float mx = 0.f;
        #pragma unroll
        for (int k = 0; k < KK; ++k) {
            float dx = rx - sm.u.a.kp[k][0];
            float dy = ry - sm.u.a.kp[k][1];
            float dz = rz - sm.u.a.kp[k][2];
            float d2 = dx * dx + dy * dy + dz * dz;
            inf[k] = fmaxf(1.0f - sqrtf(d2), 0.0f);   // SIGMA = 1
            mx = fmaxf(mx, inf[k]);
        }
        const bool any = valid && (mx > 0.0f);
        const unsigned amask = __ballot_sync(0xffffffffu, any);
        if (any) {
            const int pos = __popc(amask & lt);
            sm.u.a.sidx[ml][pos] = si;
            #pragma unroll
            for (int k = 0; k < KK; ++k)
                sm.u.a.infl[ml][pos][k] = inf[k];
            sm.u.a.infl[ml][pos][KK] = 0.0f;   // pad k=15
        }
        const unsigned nbal = __ballot_sync(0xffffffffu, valid && cs > 0.0f);
        if (lane == 0) {
            int c2 = __popc(nbal);
            sm.nnum[ml] = (float)(c2 > 0 ? c2 : 1);
        }
        const int cnt = __popc(amask);
        __syncwarp();   // warp-private smem handoff (A writes -> B reads)

        // ---- B (FFMA2, prefetched): wT[k][c][q] = sum_h infl*feat ----
        const int c = lane;
        ull wA[8], wB[8];
        #pragma unroll
        for (int j = 0; j < 8; ++j) { wA[j] = 0ull; wB[j] = 0ull; }
        uint32_t ia = (uint32_t)__cvta_generic_to_shared(&sm.u.a.infl[ml][0][0]);
        float fA = 0.f, fB = 0.f;
        if (cnt > 0) {
            const float* fp = s_feats + (size_t)sm.u.a.sidx[ml][0] * CC;
            fA = __ldg(fp + c);
            fB = __ldg(fp + c + 32);
        }
        for (int h = 0; h < cnt; ++h) {
            const int hn = (h + 1 < cnt) ? h + 1 : h;
            const float* fpn = s_feats + (size_t)sm.u.a.sidx[ml][hn] * CC;
            const float fAn = __ldg(fpn + c);
            const float fBn = __ldg(fpn + c + 32);
            const ull a2 = pack2(fA, fA);
            const ull b2 = pack2(fB, fB);
            ull v0, v1, v2, v3, v4, v5, v6, v7;
            lds2(ia,      v0, v1);
            lds2(ia + 16, v2, v3);
            lds2(ia + 32, v4, v5);
            lds2(ia + 48, v6, v7);
            fma2(wA[0], v0, a2);  fma2(wB[0], v0, b2);
            fma2(wA[1], v1, a2);  fma2(wB[1], v1, b2);
            fma2(wA[2], v2, a2);  fma2(wB[2], v2, b2);
            fma2(wA[3], v3, a2);  fma2(wB[3], v3, b2);
            fma2(wA[4], v4, a2);  fma2(wB[4], v4, b2);
            fma2(wA[5], v5, a2);  fma2(wB[5], v5, b2);
            fma2(wA[6], v6, a2);  fma2(wB[6], v6, b2);
            fma2(wA[7], v7, a2);  fma2(wB[7], v7, b2);
            fA = fAn; fB = fBn;
            ia += KP * 4;
        }
        #pragma unroll
        for (int j = 0; j < 7; ++j) {
            float2 tA = unpack2(wA[j]);
            float2 tB = unpack2(wB[j]);
            sm.wT[2 * j][c][ml]          = tA.x;
            sm.wT[2 * j + 1][c][ml]      = tA.y;
            sm.wT[2 * j][c + 32][ml]     = tB.x;
            sm.wT[2 * j + 1][c + 32][ml] = tB.y;
        }
        {
            float2 tA = unpack2(wA[7]);
            float2 tB = unpack2(wB[7]);
            sm.wT[14][c][ml]      = tA.x;
            sm.wT[14][c + 32][ml] = tB.x;
        }
    }
    __syncthreads();

    // ---- Stage C (FFMA2, balanced flattened (k,c) partition) ----
    // thread = (ks = warp, ch = c parity, dq). 480 pair-steps, 60/warp,
    // uniform pointer increments. A-pairs via two 16B broadcasts (WTP=12
    // makes every c-row 16B-aligned). Depth-1 prefetch on the W float4.
    {
        const int ks = tid >> 5;
        const int ch = (tid >> 4) & 1;
        const int dq = tid & 15;
        ull acc[4][4];
        #pragma unroll
        for (int i = 0; i < 4; ++i)
            #pragma unroll
            for (int j = 0; j < 4; ++j) acc[i][j] = 0ull;

#define CBODY(bv, aaddr)                                              \
        {                                                             \
            const ull bx = pack2((bv).x, (bv).x);                     \
            const ull by = pack2((bv).y, (bv).y);                     \
            const ull bz = pack2((bv).z, (bv).z);                     \
            const ull bw = pack2((bv).w, (bv).w);                     \
            ull a0, a1, a2, a3;                                       \
            lds2((aaddr), a0, a1);                                    \
            lds2((aaddr) + 16, a2, a3);                               \
            fma2(acc[0][0], a0, bx); fma2(acc[0][1], a0, by);         \
            fma2(acc[0][2], a0, bz); fma2(acc[0][3], a0, bw);         \
            fma2(acc[1][0], a1, bx); fma2(acc[1][1], a1, by);         \
            fma2(acc[1][2], a1, bz); fma2(acc[1][3], a1, bw);         \
            fma2(acc[2][0], a2, bx); fma2(acc[2][1], a2, by);         \
            fma2(acc[2][2], a2, bz); fma2(acc[2][3], a2, bw);         \
            fma2(acc[3][0], a3, bx); fma2(acc[3][1], a3, by);         \
            fma2(acc[3][2], a3, bz); fma2(acc[3][3], a3, bw);         \
        }

        const int u0 = 60 * ks;   // 480 pair-steps total, 60 per warp
        const float4* wp = reinterpret_cast<const float4*>(weights)
                           + (size_t)u0 * 32 + ch * (CC / 4) + dq;
        uint32_t aa = (uint32_t)__cvta_generic_to_shared(&sm.wT[0][0][0])
                      + (2 * u0 + ch) * (WTP * 4);
        float4 b = __ldg(wp);
        #pragma unroll 4
        for (int u = 0; u < 59; ++u) {
            wp += 2 * (CC / 4);              // next c of this parity
            const float4 bn = __ldg(wp);
            CBODY(b, aa);
            aa += 2 * WTP * 4;
            b = bn;
        }
        CBODY(b, aa);                        // peeled last step
#undef CBODY

        const uint32_t part_s =
            (uint32_t)__cvta_generic_to_shared(&sm.u.part[ks][0][0]);
        #pragma unroll
        for (int i = 0; i < 4; ++i) {
            #pragma unroll
            for (int j = 0; j < 4; ++j) {
                const ull o = __shfl_xor_sync(0xffffffffu, acc[i][j], 16);
                float2 s = unpack2(acc[i][j]);
                const float2 t = unpack2(o);
                s.x += t.x; s.y += t.y;
                if (ch == 0)
                    sts64(part_s + ((4 * dq + j) * PTP + 2 * i) * 4,
                          pack2(s.x, s.y));
            }
        }
    }
    __syncthreads();

    // ---- Reduce over 8 partial groups, normalize, store ----
    {
        const int q = tid >> 5;
        const int d = tid & 31;
        const int m = m0 + q;
        if (m < M) {
            float oa = 0.f, ob = 0.f;
            #pragma unroll
            for (int ks = 0; ks < 8; ++ks) {
                oa += sm.u.part[ks][d][q];
                ob += sm.u.part[ks][d + 32][q];
            }
            const float nn = sm.nnum[q];
            out[(size_t)m * CC + d]      = oa / nn;
            out[(size_t)m * CC + d + 32] = ob / nn;
        }
    }
}

extern "C" void kernel_launch(void* const* d_in, const int* in_sizes, int n_in,
                              void* d_out, int out_size)
{
    const float* q_points      = (const float*)d_in[0];  // (M,3)
    const float* s_points      = (const float*)d_in[1];  // (N,3)
    const float* s_feats       = (const float*)d_in[2];  // (N,64)
    const void*  neighbor_idx  = d_in[3];                // (M,32) int32/int64
    const float* kernel_points = (const float*)d_in[4];  // (15,3)
    const float* weights       = (const float*)d_in[5];  // (15,64,64)
    float*       out           = (float*)d_out;          // (M,64)

    const int M = in_sizes[0] / 3;
    const int N = in_sizes[1] / 3;

    colsum_kernel<<<(N + 31) / 32, NTHREADS>>>(s_feats, N);

    cudaFuncSetAttribute(kpconv_kernel,
                         cudaFuncAttributeMaxDynamicSharedMemorySize,
                         (int)sizeof(Smem));
    const int blocks = (M + QT - 1) / QT;
    kpconv_kernel<<<blocks, NTHREADS, sizeof(Smem)>>>(
        q_points, s_points, s_feats, neighbor_idx, kernel_points, weights,
        out, M, N);
}

// round 16
// speedup vs baseline: 1.1907x; 1.1907x over previous
#include <cuda_runtime.h>
#include <cstdint>

// KPConv fused: FFMA2 + compaction + QT=8 (3 CTA/SM) + balanced flattened
// Stage-C GEMM + warp-fused A+B + conflict-free swizzled partial stores +
// approx rsqrt/rcp (error ~2^-22, tolerance 1e-3). R14 base (WTP=10).

#define QT 8
#define HN 32
#define KK 15
#define KP 16
#define CC 64
#define NTHREADS 256
#define MAXN 65536
#define WTP 10       // wT q-stride (floats)
#define PTP 10       // part q-stride (floats)

typedef unsigned long long ull;

__device__ __forceinline__ ull pack2(float lo, float hi) {
    ull r; asm("mov.b64 %0, {%1, %2};" : "=l"(r) : "f"(lo), "f"(hi)); return r;
}
__device__ __forceinline__ void fma2(ull& d, ull a, ull b) {
    asm("fma.rn.f32x2 %0, %1, %2, %0;" : "+l"(d) : "l"(a), "l"(b));
}
__device__ __forceinline__ float2 unpack2(ull v) {
    float2 r; asm("mov.b64 {%0, %1}, %2;" : "=f"(r.x), "=f"(r.y) : "l"(v)); return r;
}
__device__ __forceinline__ ull lds64(uint32_t a) {
    ull r; asm volatile("ld.shared.b64 %0, [%1];" : "=l"(r) : "r"(a)); return r;
}
__device__ __forceinline__ void lds2(uint32_t a, ull& x, ull& y) {
    asm volatile("ld.shared.v2.u64 {%0, %1}, [%2];" : "=l"(x), "=l"(y) : "r"(a));
}
__device__ __forceinline__ void sts64(uint32_t a, ull v) {
    asm volatile("st.shared.b64 [%0], %1;" :: "r"(a), "l"(v) : "memory");
}
__device__ __forceinline__ float rsqrt_fast(float x) {
    float r; asm("rsqrt.approx.f32 %0, %1;" : "=f"(r) : "f"(x)); return r;
}
__device__ __forceinline__ float rcp_fast(float x) {
    float r; asm("rcp.approx.f32 %0, %1;" : "=f"(r) : "f"(x)); return r;
}

__device__ float g_colsum[MAXN];
__device__ int g_idx64;
__constant__ float c_kp[KK * 3];

// 4 rows per warp, float4 reads, 3-level 8-lane reduce.
// Block 0 warp 0 additionally probes the neighbor-index dtype:
// int64 indices (values <= N < 2^31) have all-zero odd 32-bit words.
__global__ void colsum_kernel(const float* __restrict__ s_feats,
                              const int* __restrict__ idx_words, int N) {
    const int lane = threadIdx.x & 31;
    if (blockIdx.x == 0 && threadIdx.x < 32) {
        int odd = idx_words[2 * lane + 1] | idx_words[2 * (lane + 32) + 1];
        unsigned bal = __ballot_sync(0xffffffffu, odd != 0);
        if (lane == 0) g_idx64 = (bal == 0u);
    }
    const int gw = (blockIdx.x * blockDim.x + threadIdx.x) >> 5;
    const int r = gw * 4 + (lane >> 3);
    const int rr = (r < N) ? r : (N - 1);
    const float4* fp = reinterpret_cast<const float4*>(s_feats + (size_t)rr * CC);
    const float4 a = fp[(lane & 7) * 2];
    const float4 b = fp[(lane & 7) * 2 + 1];
    float s = a.x + a.y + a.z + a.w + b.x + b.y + b.z + b.w;
    s += __shfl_xor_sync(0xffffffffu, s, 4);
    s += __shfl_xor_sync(0xffffffffu, s, 2);
    s += __shfl_xor_sync(0xffffffffu, s, 1);
    if ((lane & 7) == 0 && r < N) g_colsum[r] = s;
}

struct __align__(16) Smem {
    union {
        struct {
            float infl[QT][HN][KP];     // compacted influence rows
            int   sidx[QT][HN];
        } a;
        float part[8][CC][PTP];         // stage-C partials (overwrites a)
    } u;
    float wT[KK][CC][WTP];              // weighted, transposed [k][c][q]
    float nnum[QT];
};

__global__ __launch_bounds__(NTHREADS, 3)
void kpconv_kernel(const float* __restrict__ q_points,
                   const float* __restrict__ s_points,
                   const float* __restrict__ s_feats,
                   const void* __restrict__ nbr_idx_raw,
                   const float* __restrict__ weights,
                   float* __restrict__ out,
                   int M, int N)
{
    extern __shared__ __align__(16) char smem_raw[];
    Smem& sm = *reinterpret_cast<Smem*>(smem_raw);
    const int tid = threadIdx.x;
    const int m0 = blockIdx.x * QT;
    const int idx64 = g_idx64;      // written by colsum_kernel (stream-ordered)

    // ================= Stage A+B fused per warp (warp = query) =============
    {
        const int lane = tid & 31;
        const int ml = tid >> 5;
        const unsigned lt = (1u << lane) - 1u;
        const int m = m0 + ml;

        // ---- A: influence + compaction + neighbor count ----
        bool valid = false;
        int si = 0;
        float rx = 0.f, ry = 0.f, rz = 0.f, cs = 0.f;
        if (m < M) {
            long long gi;
            if (idx64)
                gi = reinterpret_cast<const long long*>(nbr_idx_raw)[(long long)m * HN + lane];
            else
                gi = reinterpret_cast<const int*>(nbr_idx_raw)[(long long)m * HN + lane];
            if (gi < (long long)N) { valid = true; si = (int)gi; }
        }
        if (valid) {
            rx = s_points[si * 3 + 0] - q_points[m * 3 + 0];
            ry = s_points[si * 3 + 1] - q_points[m * 3 + 1];
            rz = s_points[si * 3 + 2] - q_points[m * 3 + 2];
            cs = g_colsum[si];
        }
        float inf[KK];
        float mx = 0.f;
        #pragma unroll
        for (int k = 0; k < KK; ++k) {
            float dx = rx - c_kp[k * 3 + 0];
            float dy = ry - c_kp[k * 3 + 1];
            float dz = rz - c_kp[k * 3 + 2];
            float d2 = fmaxf(dx * dx + dy * dy + dz * dz, 1e-30f);
            // 1 - sqrt(d2) via rsqrt.approx: rel err ~2^-22, tol is 1e-3
            inf[k] = fmaxf(1.0f - d2 * rsqrt_fast(d2), 0.0f);   // SIGMA = 1
            mx = fmaxf(mx, inf[k]);
        }
        const bool any = valid && (mx > 0.0f);
        const unsigned amask = __ballot_sync(0xffffffffu, any);
        if (any) {
            const int pos = __popc(amask & lt);
            sm.u.a.sidx[ml][pos] = si;
            #pragma unroll
            for (int k = 0; k < KK; ++k)
                sm.u.a.infl[ml][pos][k] = inf[k];
            sm.u.a.infl[ml][pos][KK] = 0.0f;   // pad k=15
        }
        const unsigned nbal = __ballot_sync(0xffffffffu, valid && cs > 0.0f);
        if (lane == 0) {
            int c2 = __popc(nbal);
            sm.nnum[ml] = (float)(c2 > 0 ? c2 : 1);
        }
        const int cnt = __popc(amask);
        __syncwarp();   // warp-private smem handoff (A writes -> B reads)

        // ---- B (FFMA2, prefetched): wT[k][c][q] = sum_h infl*feat ----
        const int c = lane;
        ull wA[8], wB[8];
        #pragma unroll
        for (int j = 0; j < 8; ++j) { wA[j] = 0ull; wB[j] = 0ull; }
        uint32_t ia = (uint32_t)__cvta_generic_to_shared(&sm.u.a.infl[ml][0][0]);
        float fA = 0.f, fB = 0.f;
        if (cnt > 0) {
            const float* fp = s_feats + (size_t)sm.u.a.sidx[ml][0] * CC;
            fA = __ldg(fp + c);
            fB = __ldg(fp + c + 32);
        }
        for (int h = 0; h < cnt; ++h) {
            const int hn = (h + 1 < cnt) ? h + 1 : h;
            const float* fpn = s_feats + (size_t)sm.u.a.sidx[ml][hn] * CC;
            const float fAn = __ldg(fpn + c);
            const float fBn = __ldg(fpn + c + 32);
            const ull a2 = pack2(fA, fA);
            const ull b2 = pack2(fB, fB);
            ull v0, v1, v2, v3, v4, v5, v6, v7;
            lds2(ia,      v0, v1);
            lds2(ia + 16, v2, v3);
            lds2(ia + 32, v4, v5);
            lds2(ia + 48, v6, v7);
            fma2(wA[0], v0, a2);  fma2(wB[0], v0, b2);
            fma2(wA[1], v1, a2);  fma2(wB[1], v1, b2);
            fma2(wA[2], v2, a2);  fma2(wB[2], v2, b2);
            fma2(wA[3], v3, a2);  fma2(wB[3], v3, b2);
            fma2(wA[4], v4, a2);  fma2(wB[4], v4, b2);
            fma2(wA[5], v5, a2);  fma2(wB[5], v5, b2);
            fma2(wA[6], v6, a2);  fma2(wB[6], v6, b2);
            fma2(wA[7], v7, a2);  fma2(wB[7], v7, b2);
            fA = fAn; fB = fBn;
            ia += KP * 4;
        }
        #pragma unroll
        for (int j = 0; j < 7; ++j) {
            float2 tA = unpack2(wA[j]);
            float2 tB = unpack2(wB[j]);
            sm.wT[2 * j][c][ml]          = tA.x;
            sm.wT[2 * j + 1][c][ml]      = tA.y;
            sm.wT[2 * j][c + 32][ml]     = tB.x;
            sm.wT[2 * j + 1][c + 32][ml] = tB.y;
        }
        {
            float2 tA = unpack2(wA[7]);
            float2 tB = unpack2(wB[7]);
            sm.wT[14][c][ml]      = tA.x;
            sm.wT[14][c + 32][ml] = tB.x;
        }
    }
    __syncthreads();

    // ---- Stage C (FFMA2, balanced flattened (k,c) partition) ----
    // thread = (ks = warp, ch = c parity, dq). 480 pair-steps, 60/warp,
    // uniform pointer increments. Depth-1 prefetch on the W float4.
    {
        const int ks = tid >> 5;
        const int ch = (tid >> 4) & 1;
        const int dq = tid & 15;
        ull acc[4][4];
        #pragma unroll
        for (int i = 0; i < 4; ++i)
            #pragma unroll
            for (int j = 0; j < 4; ++j) acc[i][j] = 0ull;

#define CBODY(bv, aaddr)                                              \
        {                                                             \
            const ull bx = pack2((bv).x, (bv).x);                     \
            const ull by = pack2((bv).y, (bv).y);                     \
            const ull bz = pack2((bv).z, (bv).z);                     \
            const ull bw = pack2((bv).w, (bv).w);                     \
            const ull a0 = lds64(aaddr);                              \
            const ull a1 = lds64((aaddr) + 8);                        \
            const ull a2 = lds64((aaddr) + 16);                       \
            const ull a3 = lds64((aaddr) + 24);                       \
            fma2(acc[0][0], a0, bx); fma2(acc[0][1], a0, by);         \
            fma2(acc[0][2], a0, bz); fma2(acc[0][3], a0, bw);         \
            fma2(acc[1][0], a1, bx); fma2(acc[1][1], a1, by);         \
            fma2(acc[1][2], a1, bz); fma2(acc[1][3], a1, bw);         \
            fma2(acc[2][0], a2, bx); fma2(acc[2][1], a2, by);         \
            fma2(acc[2][2], a2, bz); fma2(acc[2][3], a2, bw);         \
            fma2(acc[3][0], a3, bx); fma2(acc[3][1], a3, by);         \
            fma2(acc[3][2], a3, bz); fma2(acc[3][3], a3, bw);         \
        }

        const int u0 = 60 * ks;   // 480 pair-steps total, 60 per warp
        const float4* wp = reinterpret_cast<const float4*>(weights)
                           + (size_t)u0 * 32 + ch * (CC / 4) + dq;
        uint32_t aa = (uint32_t)__cvta_generic_to_shared(&sm.wT[0][0][0])
                      + (2 * u0 + ch) * (WTP * 4);
        float4 b = __ldg(wp);
        #pragma unroll 4
        for (int u = 0; u < 59; ++u) {
            wp += 2 * (CC / 4);              // next c of this parity
            const float4 bn = __ldg(wp);
            CBODY(b, aa);
            aa += 2 * WTP * 4;
            b = bn;
        }
        CBODY(b, aa);                        // peeled last step
#undef CBODY

        // Swizzled partial stores: column q' = (2i + sC) & 7 with
        // sC = 2*((dq>>2)&3) makes the 16-lane sts64 conflict-free
        // (banks 8dq + sC mod 32 are all distinct; 16 x 8B = all 32 banks).
        const int sC = 2 * ((dq >> 2) & 3);
        const uint32_t part_s =
            (uint32_t)__cvta_generic_to_shared(&sm.u.part[ks][0][0]);
        #pragma unroll
        for (int i = 0; i < 4; ++i) {
            #pragma unroll
            for (int j = 0; j < 4; ++j) {
                const ull o = __shfl_xor_sync(0xffffffffu, acc[i][j], 16);
                float2 s = unpack2(acc[i][j]);
                const float2 t = unpack2(o);
                s.x += t.x; s.y += t.y;
                if (ch == 0)
                    sts64(part_s + ((4 * dq + j) * PTP + ((2 * i + sC) & 7)) * 4,
                          pack2(s.x, s.y));
            }
        }
    }
    __syncthreads();

    // ---- Reduce over 8 partial groups (un-swizzle), normalize, store ----
    {
        const int q = tid >> 5;
        const int d = tid & 31;
        const int m = m0 + q;
        if (m < M) {
            // store swizzle sC depended on dq = d>>2 (low half) / d>>2+8 (high)
            const int qLo = (q + 2 * ((d >> 4) & 3)) & 7;
            const int qHi = (q + 2 * (((d >> 4) + 2) & 3)) & 7;
            float oa = 0.f, ob = 0.f;
            #pragma unroll
            for (int ks = 0; ks < 8; ++ks) {
                oa += sm.u.part[ks][d][qLo];
                ob += sm.u.part[ks][d + 32][qHi];
            }
            const float rn = rcp_fast(sm.nnum[q]);
            out[(size_t)m * CC + d]      = oa * rn;
            out[(size_t)m * CC + d + 32] = ob * rn;
        }
    }
}

extern "C" void kernel_launch(void* const* d_in, const int* in_sizes, int n_in,
                              void* d_out, int out_size)
{
    const float* q_points      = (const float*)d_in[0];  // (M,3)
    const float* s_points      = (const float*)d_in[1];  // (N,3)
    const float* s_feats       = (const float*)d_in[2];  // (N,64)
    const void*  neighbor_idx  = d_in[3];                // (M,32) int32/int64
    const float* kernel_points = (const float*)d_in[4];  // (15,3)
    const float* weights       = (const float*)d_in[5];  // (15,64,64)
    float*       out           = (float*)d_out;          // (M,64)

    const int M = in_sizes[0] / 3;
    const int N = in_sizes[1] / 3;

    // kernel points -> constant memory (capturable D2D copy)
    cudaMemcpyToSymbolAsync(c_kp, kernel_points, KK * 3 * sizeof(float), 0,
                            cudaMemcpyDeviceToDevice);

    colsum_kernel<<<(N + 31) / 32, NTHREADS>>>(s_feats,
                                               (const int*)neighbor_idx, N);

    cudaFuncSetAttribute(kpconv_kernel,
                         cudaFuncAttributeMaxDynamicSharedMemorySize,
                         (int)sizeof(Smem));
    const int blocks = (M + QT - 1) / QT;
    kpconv_kernel<<<blocks, NTHREADS, sizeof(Smem)>>>(
        q_points, s_points, s_feats, neighbor_idx, weights,
        out, M, N);
}